// round 13
// baseline (speedup 1.0000x reference)
#include <cuda_runtime.h>
#include <cuda_fp16.h>

#define TT 32

// Device-global scratch: Whh fp16 row-major padded [512][136] (272B rows)
__device__ __half g_WhhH[512 * 136];

__device__ __forceinline__ float fast_tanh(float x) {
    float y;
    asm("tanh.approx.f32 %0, %1;" : "=f"(y) : "f"(x));
    return y;
}
__device__ __forceinline__ float fast_sig(float x) {
    return 0.5f + 0.5f * fast_tanh(0.5f * x);
}
__device__ __forceinline__ unsigned packh2(float x, float y) {
    __half2 h = __floats2half2_rn(x, y);
    return *reinterpret_cast<unsigned*>(&h);
}

#define MMA16816(d0,d1,d2,d3,a0,a1,a2,a3,b0,b1)                              \
    asm volatile(                                                            \
        "mma.sync.aligned.m16n8k16.row.col.f32.f16.f16.f32 "                 \
        "{%0,%1,%2,%3}, {%4,%5,%6,%7}, {%8,%9}, {%0,%1,%2,%3};"              \
        : "+f"(d0), "+f"(d1), "+f"(d2), "+f"(d3)                             \
        : "r"(a0), "r"(a1), "r"(a2), "r"(a3), "r"(b0), "r"(b1))

// per-group named barrier (group 0 -> id 1, group 1 -> id 2), 256 threads
#define BARG(gid) asm volatile("bar.sync %0, 256;" :: "r"((gid) + 1) : "memory")

// fp32 master hc: quarters of 64 floats at stride 68; batch stride 272.
#define HQ 68
#define HB 272

// ---------------------------------------------------------------------------
// Prep: Whh fp32 -> fp16 row-major padded [512][136]
// ---------------------------------------------------------------------------
__global__ void __launch_bounds__(128)
whh_prep(const float* __restrict__ Whh)   // [512,128]
{
    int base = blockIdx.x * 8704;
    for (int i = base + threadIdx.x; i < base + 8704; i += 128) {
        int r = i / 136, k = i % 136;
        g_WhhH[i] = __float2half((k < 128) ? Whh[r * 128 + k] : 0.f);
    }
}

// ---------------------------------------------------------------------------
// Main: 128 blocks x 512 threads. Warps 0-7 = batch0 pipeline, 8-15 = batch1.
// Each group: {A+F} | bar | B | bar | G' | bar with its own named barrier.
// ---------------------------------------------------------------------------
__global__ void __launch_bounds__(512, 1)
decoder_kernel(const float* __restrict__ enc,     // [B,32,128]
               const float* __restrict__ yhist,   // [B,32]
               const float* __restrict__ W1,      // [128,384] cols [h|c|enc]
               const float* __restrict__ b1,      // [128]
               const float* __restrict__ W2,      // [128]
               const float* __restrict__ Wih,     // [512]
               const float* __restrict__ bih,     // [512]
               const float* __restrict__ bhh,     // [512]
               const float* __restrict__ fcW,     // [129]
               const float* __restrict__ fcb,     // [1]
               const float* __restrict__ fcfW,    // [256]
               const float* __restrict__ fcfb,    // [1]
               float* __restrict__ out)           // [256]
{
    extern __shared__ float sm[];
    __half* sWh   = (__half*)sm;          // [512][136] fp16 = 34816 fl
    float*  sEnc  = sm + 34816;           // 8448 [64 rows][132]
    float*  sE1   = sEnc + 8448;          // 8448 [64 rows][132]
    float*  sHp   = sE1 + 8448;           // 552  fp32 master hc [g][q][68]
    __half* sHch  = (__half*)(sHp + 552); // per group: [2][264] halves (row1=0)
    float*  sgates= sHp + 552 + 528;      // 1024 [g][512]
    float*  sup   = sgates + 1024;        // 264  [g][132]
    float*  sctxC = sup + 264;            // 256  [g][128]
    float*  sWih  = sctxC + 256;          // 512
    float*  sbias = sWih + 512;           // 512
    float*  sW2   = sbias + 512;          // 128
    float*  sfcf  = sW2 + 128;            // 256
    float*  sfc   = sfcf + 256;           // 132
    float*  sy    = sfc + 132;            // 64  [g][32]
    float*  slogS = sy + 64;              // 64  [g][32]
    float*  sEf   = slogS + 64;           // 64  [g][32]
    float*  sAtt  = sEf + 64;             // 64  [g][32]

    const int tid  = threadIdx.x;
    const int lane = tid & 31;
    const int warp = tid >> 5;
    const int bp   = blockIdx.x * 2;
    const int g    = warp >> 3;    // pipeline group = batch-in-block
    const int wg   = warp & 7;     // warp within group
    const int gtid = tid & 255;

    // MMA lane coordinates
    const int tg = lane & 3;
    const int g8 = lane >> 2;

    // ---- load phase (full block) ----
    for (int i = tid; i < 8704; i += 512)
        reinterpret_cast<uint4*>(sWh)[i] =
            reinterpret_cast<const uint4*>(g_WhhH)[i];
    for (int i4 = tid; i4 < 2048; i4 += 512) {
        int r = i4 >> 5, c = i4 & 31;
        reinterpret_cast<float4*>(sEnc)[r * 33 + c] =
            reinterpret_cast<const float4*>(enc + (size_t)bp * 4096)[i4];
    }
    sWih[tid]  = Wih[tid];
    sbias[tid] = bih[tid] + bhh[tid];
    if (tid < 552) sHp[tid] = 0.f;
    if (tid < 528) reinterpret_cast<float*>(sHch)[tid] = 0.f;
    if (tid < 128) sW2[tid]  = W2[tid];
    if (tid < 256) sfcf[tid] = fcfW[tid];
    if (tid < 131)
        sfc[tid] = (tid < 129) ? fcW[tid] : (tid == 129) ? fcb[0] : fcfb[0];
    if (tid < 64) sy[tid] = yhist[(bp + (tid >> 5)) * 32 + (tid & 31)];
    __syncthreads();

    // ---- E1 = enc @ W1e^T + b1, in-CTA once (full block) ----
    {
        int h = tid & 127, rq = tid >> 7;
        float acc[16];
        float bb = b1[h];
#pragma unroll
        for (int rr = 0; rr < 16; rr++) acc[rr] = bb;
        const float4* wsrc = reinterpret_cast<const float4*>(W1 + h * 384 + 256);
#pragma unroll
        for (int ch = 0; ch < 4; ch++) {
            float4 w[8];
#pragma unroll
            for (int kk = 0; kk < 8; kk++) w[kk] = wsrc[ch * 8 + kk];
#pragma unroll
            for (int rr = 0; rr < 16; rr++) {
                const float4* ev = reinterpret_cast<const float4*>(
                    sEnc + (rq * 16 + rr) * 132) + ch * 8;
                float s = 0.f;
#pragma unroll
                for (int kk = 0; kk < 8; kk++) {
                    float4 e = ev[kk];
                    s += w[kk].x * e.x + w[kk].y * e.y
                       + w[kk].z * e.z + w[kk].w * e.w;
                }
                acc[rr] += s;
            }
        }
#pragma unroll
        for (int rr = 0; rr < 16; rr++)
            sE1[(rq * 16 + rr) * 132 + h] = acc[rr];
    }

    // ---- ef[p] = enc row p . fcW ----
    {
        int c8 = lane & 7, pr = lane >> 3;
        int p  = (warp << 2) | pr;   // p = g*32 + t
        const float4* er = reinterpret_cast<const float4*>(sEnc + p * 132);
        const float4* fr = reinterpret_cast<const float4*>(sfc);
        float s = 0.f;
#pragma unroll
        for (int c = 0; c < 4; c++) {
            int idx = c * 8 + c8;
            float4 e = er[idx], f = fr[idx];
            s += e.x * f.x + e.y * f.y + e.z * f.z + e.w * f.w;
        }
        s += __shfl_xor_sync(0xffffffffu, s, 1);
        s += __shfl_xor_sync(0xffffffffu, s, 2);
        s += __shfl_xor_sync(0xffffffffu, s, 4);
        if (c8 == 0) sEf[p] = s;
    }

    // ---- A persistent W1 fragments: warp covers rows j0..j0+15, full hc-k
    const int j0 = wg << 4;
    unsigned aw0[16], aw1[16], aw2[16], aw3[16];
    {
        const float* r0p = W1 + (j0 + g8) * 384 + tg * 2;
        const float* r1p = r0p + 8 * 384;
#pragma unroll
        for (int kt = 0; kt < 16; kt++) {
            int k = kt * 16;
            aw0[kt] = packh2(r0p[k],     r0p[k + 1]);
            aw1[kt] = packh2(r1p[k],     r1p[k + 1]);
            aw2[kt] = packh2(r0p[k + 8], r0p[k + 9]);
            aw3[kt] = packh2(r1p[k + 8], r1p[k + 9]);
        }
    }
    // group B-operand row (row1 of the group's shadow is permanently zero)
    const __half* bbRow = sHch + g * 528 + ((g8 >= 1) ? 264 : 0) + tg * 2;

    // F ldmatrix bases: warp covers Whh rows 64wg..64wg+63 (4 row-tiles)
    const unsigned whBase = (unsigned)__cvta_generic_to_shared(sWh);
    unsigned sF[4];
#pragma unroll
    for (int rt = 0; rt < 4; rt++)
        sF[rt] = whBase +
            (((wg << 6) + (rt << 4) + (lane & 15)) * 136 + ((lane >> 4) << 3)) * 2;

    // G' constants (used by wg<4 threads)
    const float ef_reg = sEf[(g << 5) | lane];
    const float yco = sfc[128], ycb = sfc[129];
    __syncthreads();   // last full-block barrier

    for (int step = 0; step < TT; step++) {
        // ======== phase 1: A (u = W1_hc @ hc) + F (gates = Whh @ h) ========
        {
            // A: 16 k-tiles over hc, 2 interleaved accum chains
            float A0 = 0.f, A1 = 0.f, A2 = 0.f, A3 = 0.f;
            float C0 = 0.f, C1 = 0.f, C2 = 0.f, C3 = 0.f;
#pragma unroll
            for (int kt = 0; kt < 16; kt += 2) {
                unsigned b0 = *reinterpret_cast<const unsigned*>(bbRow + kt * 16);
                unsigned b1 = *reinterpret_cast<const unsigned*>(bbRow + kt * 16 + 8);
                MMA16816(A0, A1, A2, A3,
                         aw0[kt], aw1[kt], aw2[kt], aw3[kt], b0, b1);
                unsigned c0 = *reinterpret_cast<const unsigned*>(bbRow + kt * 16 + 16);
                unsigned c1 = *reinterpret_cast<const unsigned*>(bbRow + kt * 16 + 24);
                MMA16816(C0, C1, C2, C3,
                         aw0[kt + 1], aw1[kt + 1], aw2[kt + 1], aw3[kt + 1],
                         c0, c1);
            }
            if (tg == 0) {
                float* P = sup + g * 132;
                P[j0 + g8]     = A0 + C0;
                P[j0 + g8 + 8] = A2 + C2;
            }
            // F: 4 row-tiles x 8 k-tiles (h half only)
            float f0[4] = {0.f, 0.f, 0.f, 0.f};
            float f2[4] = {0.f, 0.f, 0.f, 0.f};
            float fj[4], fk[4];   // unused cols kept for MMA shape
#pragma unroll
            for (int rt = 0; rt < 4; rt++) { fj[rt] = 0.f; fk[rt] = 0.f; }
#pragma unroll
            for (int kt = 0; kt < 8; kt++) {
                unsigned b0 = *reinterpret_cast<const unsigned*>(bbRow + kt * 16);
                unsigned b1 = *reinterpret_cast<const unsigned*>(bbRow + kt * 16 + 8);
#pragma unroll
                for (int rt = 0; rt < 4; rt++) {
                    unsigned a0, a1, a2, a3;
                    asm volatile(
                        "ldmatrix.sync.aligned.m8n8.x4.shared.b16 "
                        "{%0,%1,%2,%3}, [%4];"
                        : "=r"(a0), "=r"(a1), "=r"(a2), "=r"(a3)
                        : "r"(sF[rt] + kt * 32));
                    MMA16816(f0[rt], fj[rt], f2[rt], fk[rt],
                             a0, a1, a2, a3, b0, b1);
                }
            }
            if (tg == 0) {
                float* G = sgates + g * 512;
#pragma unroll
                for (int rt = 0; rt < 4; rt++) {
                    int r0 = (wg << 6) + (rt << 4) + g8;
                    G[r0]     = f0[rt];
                    G[r0 + 8] = f2[rt];
                }
            }
        }
        BARG(g);

        // ======== phase 2: B — 32 logits, 4 rows per warp ========
        {
            int c8 = lane & 7, pr = lane >> 3;
            int p  = (wg << 2) | pr;
            const float4* e1r = reinterpret_cast<const float4*>(
                sE1 + (g * 32 + p) * 132);
            const float4* ur  = reinterpret_cast<const float4*>(sup + g * 132);
            const float4* wr  = reinterpret_cast<const float4*>(sW2);
            float s = 0.f;
#pragma unroll
            for (int c = 0; c < 4; c++) {
                int idx = c * 8 + c8;
                float4 e = e1r[idx], u = ur[idx], w = wr[idx];
                s += fast_tanh(e.x + u.x) * w.x + fast_tanh(e.y + u.y) * w.y
                   + fast_tanh(e.z + u.z) * w.z + fast_tanh(e.w + u.w) * w.w;
            }
            s += __shfl_xor_sync(0xffffffffu, s, 1);
            s += __shfl_xor_sync(0xffffffffu, s, 2);
            s += __shfl_xor_sync(0xffffffffu, s, 4);
            if (c8 == 0) slogS[(g << 5) | p] = s;
        }
        BARG(g);

        // ======== phase 3: G' — softmax + y_tilde + LSTM cell (wg<4) ========
        if (wg < 4) {
            int j = gtid;   // 0..127
            float l = slogS[(g << 5) | lane];
            float e = __expf(l);               // logits bounded: no max pass
            float sum = e, wy = e * ef_reg;
#pragma unroll
            for (int o = 16; o > 0; o >>= 1) {
                sum += __shfl_xor_sync(0xffffffffu, sum, o);
                wy  += __shfl_xor_sync(0xffffffffu, wy, o);
            }
            float y = __fdividef(wy, sum) + sy[(g << 5) | step] * yco + ycb;
            float gv[4];
#pragma unroll
            for (int q = 0; q < 4; q++) {
                int r = q * 128 + j;
                gv[q] = sgates[g * 512 + r] + sbias[r] + y * sWih[r];
            }
            int hq = j >> 6, ho = j & 63;
            float* hb = sHp + g * HB;
            float c_old = hb[(2 + hq) * HQ + ho];
            float si = fast_sig(gv[0]);
            float sf = fast_sig(gv[1]);
            float so = fast_sig(gv[3]);
            float cn = sf * c_old + si * fast_tanh(gv[2]);
            float hn = so * fast_tanh(cn);
            hb[(2 + hq) * HQ + ho] = cn;
            hb[hq * HQ + ho]       = hn;
            __half* hr = sHch + g * 528;
            hr[j]       = __float2half(hn);
            hr[128 + j] = __float2half(cn);
            if (step == TT - 1 && wg == 0)
                sAtt[(g << 5) | lane] = __fdividef(e, sum);
        }
        BARG(g);
    }

    // ---- final ctx per group ----
    if (wg < 4) {
        int j = ((wg & 3) << 5) | lane;
        const float* eb = sEnc + (g * 32) * 132 + j;
        const float* ab = sAtt + g * 32;
        float acc = 0.f;
#pragma unroll
        for (int t = 0; t < 32; t++)
            acc = fmaf(ab[t], eb[t * 132], acc);
        sctxC[g * 128 + j] = acc;
    }
    BARG(g);

    // ---- final: out[b] = [h, ctx] . fcfW + fcfb + y_history[b, 31]
    if (wg == 0) {
        float4 hv = reinterpret_cast<const float4*>(sHp + g * HB)
                        [(lane >> 4) * 17 + (lane & 15)];
        float4 f1 = reinterpret_cast<const float4*>(sfcf)[lane];
        float4 cv = reinterpret_cast<const float4*>(sctxC + g * 128)[lane];
        float4 f2 = reinterpret_cast<const float4*>(sfcf + 128)[lane];
        float s = hv.x * f1.x + hv.y * f1.y + hv.z * f1.z + hv.w * f1.w
                + cv.x * f2.x + cv.y * f2.y + cv.z * f2.z + cv.w * f2.w;
#pragma unroll
        for (int o = 16; o > 0; o >>= 1)
            s += __shfl_xor_sync(0xffffffffu, s, o);
        if (lane == 0)
            out[bp + g] = s + sfc[130] + sy[(g << 5) | 31];
    }
}

// ---------------------------------------------------------------------------
extern "C" void kernel_launch(void* const* d_in, const int* in_sizes, int n_in,
                              void* d_out, int out_size)
{
    const float* enc  = (const float*)d_in[0];
    const float* yh   = (const float*)d_in[1];
    const float* W1   = (const float*)d_in[2];
    const float* b1   = (const float*)d_in[3];
    const float* W2   = (const float*)d_in[4];
    // d_in[5] = attn_b2 : constant shift, cancels in softmax
    const float* Wih  = (const float*)d_in[6];
    const float* Whh  = (const float*)d_in[7];
    const float* bih  = (const float*)d_in[8];
    const float* bhh  = (const float*)d_in[9];
    const float* fcW  = (const float*)d_in[10];
    const float* fcb  = (const float*)d_in[11];
    const float* fcfW = (const float*)d_in[12];
    const float* fcfb = (const float*)d_in[13];
    float* out = (float*)d_out;

    const size_t smem_floats = 34816 + 8448 + 8448 + 552 + 528 + 1024
                             + 264 + 256 + 512 + 512 + 128 + 256 + 132
                             + 64 + 64 + 64 + 64;
    const size_t smem = smem_floats * sizeof(float);   // 224,528 B

    cudaFuncSetAttribute(decoder_kernel,
                         cudaFuncAttributeMaxDynamicSharedMemorySize, (int)smem);
    cudaFuncSetAttribute(decoder_kernel,
                         cudaFuncAttributePreferredSharedMemoryCarveout, 100);

    whh_prep<<<8, 128>>>(Whh);
    decoder_kernel<<<128, 512, smem>>>(enc, yh, W1, b1, W2, Wih, bih, bhh,
                                       fcW, fcb, fcfW, fcfb, out);
}

// round 14
// speedup vs baseline: 1.1365x; 1.1365x over previous
#include <cuda_runtime.h>
#include <cuda_fp16.h>

#define BB 256
#define TT 32

// Device-global scratch: Whh fp16 row-major padded [512][136] (272B rows)
__device__ __half g_WhhH[512 * 136];

__device__ __forceinline__ float fast_tanh(float x) {
    float y;
    asm("tanh.approx.f32 %0, %1;" : "=f"(y) : "f"(x));
    return y;
}
__device__ __forceinline__ float fast_sig(float x) {
    return 0.5f + 0.5f * fast_tanh(0.5f * x);
}
__device__ __forceinline__ unsigned packh2(float x, float y) {
    __half2 h = __floats2half2_rn(x, y);
    return *reinterpret_cast<unsigned*>(&h);
}

#define MMA16816(d0,d1,d2,d3,a0,a1,a2,a3,b0,b1)                              \
    asm volatile(                                                            \
        "mma.sync.aligned.m16n8k16.row.col.f32.f16.f16.f32 "                 \
        "{%0,%1,%2,%3}, {%4,%5,%6,%7}, {%8,%9}, {%0,%1,%2,%3};"              \
        : "+f"(d0), "+f"(d1), "+f"(d2), "+f"(d3)                             \
        : "r"(a0), "r"(a1), "r"(a2), "r"(a3), "r"(b0), "r"(b1))

// fp32 h master: quarters of 64 floats at stride 68; batch stride 272.
#define HQ 68
#define HB 272
// fp16 hc shadow rows: 264 halves per row (paired-quad layout inside).
#define HCS 264

// paired-quad slot for k-index-within-16: quad tg owns halves [4tg..4tg+3]
// = original {2tg, 2tg+1, 2tg+8, 2tg+9}
__device__ __forceinline__ int pslot(int r) {
    return (((r & 7) >> 1) << 2) | (((r >> 3) & 1) << 1) | (r & 1);
}

// ---------------------------------------------------------------------------
// Prep: Whh fp32 -> fp16 row-major padded [512][136]
// ---------------------------------------------------------------------------
__global__ void __launch_bounds__(128)
whh_prep(const float* __restrict__ Whh)   // [512,128]
{
    int base = blockIdx.x * 8704;
    for (int i = base + threadIdx.x; i < base + 8704; i += 128) {
        int r = i / 136, k = i % 136;
        g_WhhH[i] = __float2half((k < 128) ? Whh[r * 128 + k] : 0.f);
    }
}

// ---------------------------------------------------------------------------
// Main: 128 blocks x 512 threads, 2 batches/block. 3 barriers per step.
// A and F on tensor cores; ctx eliminated from the loop; c-state in regs.
// ---------------------------------------------------------------------------
__global__ void __launch_bounds__(512, 1)
decoder_kernel(const float* __restrict__ enc,     // [B,32,128]
               const float* __restrict__ yhist,   // [B,32]
               const float* __restrict__ W1,      // [128,384] cols [h|c|enc]
               const float* __restrict__ b1,      // [128]
               const float* __restrict__ W2,      // [128]
               const float* __restrict__ Wih,     // [512]
               const float* __restrict__ bih,     // [512]
               const float* __restrict__ bhh,     // [512]
               const float* __restrict__ fcW,     // [129]
               const float* __restrict__ fcb,     // [1]
               const float* __restrict__ fcfW,    // [256]
               const float* __restrict__ fcfb,    // [1]
               float* __restrict__ out)           // [256]
{
    extern __shared__ float sm[];
    __half* sWh   = (__half*)sm;          // [512][136] fp16 = 34816 fl
    float*  sEnc  = sm + 34816;           // 8448 [64 rows][132]
    float*  sE1   = sEnc + 8448;          // 8448 [64 rows][132]
    float*  sHp   = sE1 + 8448;           // 552  fp32 h master [g][q][68]
    __half* sHch  = (__half*)(sHp + 552); // [8][264] fp16 hc shadow (paired)
    float*  sgates= sHp + 552 + 1056;     // 1024 [g][512]
    float*  sup   = sgates + 1024;        // 528  [kh][g][132] u partials
    float*  sctxC = sup + 528;            // 256  [g][128] final ctx only
    float*  sWih  = sctxC + 256;          // 512
    float*  sbias = sWih + 512;           // 512
    float*  sW2   = sbias + 512;          // 128
    float*  sfcf  = sW2 + 128;            // 256
    float*  sfc   = sfcf + 256;           // 132: fcW[0..129), [129]=fcb, [130]=fcfb
    float*  sy    = sfc + 132;            // 64  [g][32]
    float*  slogS = sy + 64;              // 64
    float*  sEf   = slogS + 64;           // 64  [g][32] enc_t . fcW
    float*  sAtt  = sEf + 64;             // 64  [g][32] last-step attn

    const int tid  = threadIdx.x;
    const int lane = tid & 31;
    const int warp = tid >> 5;
    const int bp   = blockIdx.x * 2;

    // MMA lane coordinates
    const int tg = lane & 3;     // quad id (k selector)
    const int g8 = lane >> 2;    // group id (row / col-n selector)

    // ---- load phase ----
    for (int i = tid; i < 8704; i += 512)
        reinterpret_cast<uint4*>(sWh)[i] =
            reinterpret_cast<const uint4*>(g_WhhH)[i];
    for (int i4 = tid; i4 < 2048; i4 += 512) {
        int r = i4 >> 5, c = i4 & 31;
        reinterpret_cast<float4*>(sEnc)[r * 33 + c] =
            reinterpret_cast<const float4*>(enc + (size_t)bp * 4096)[i4];
    }
    sWih[tid]  = Wih[tid];
    sbias[tid] = bih[tid] + bhh[tid];
    if (tid < 552) sHp[tid] = 0.f;
    for (int i = tid; i < 1056; i += 512)
        reinterpret_cast<float*>(sHch)[i] = 0.f;
    if (tid < 128) sW2[tid]  = W2[tid];
    if (tid < 256) sfcf[tid] = fcfW[tid];
    if (tid < 131)
        sfc[tid] = (tid < 129) ? fcW[tid] : (tid == 129) ? fcb[0] : fcfb[0];
    if (tid < 64) sy[tid] = yhist[(bp + (tid >> 5)) * 32 + (tid & 31)];
    __syncthreads();

    // ---- E1 = enc @ W1e^T + b1, in-CTA once ----
    {
        int h = tid & 127, rq = tid >> 7;
        float acc[16];
        float bb = b1[h];
#pragma unroll
        for (int rr = 0; rr < 16; rr++) acc[rr] = bb;
        const float4* wsrc = reinterpret_cast<const float4*>(W1 + h * 384 + 256);
#pragma unroll
        for (int ch = 0; ch < 4; ch++) {
            float4 w[8];
#pragma unroll
            for (int kk = 0; kk < 8; kk++) w[kk] = wsrc[ch * 8 + kk];
#pragma unroll
            for (int rr = 0; rr < 16; rr++) {
                const float4* ev = reinterpret_cast<const float4*>(
                    sEnc + (rq * 16 + rr) * 132) + ch * 8;
                float s = 0.f;
#pragma unroll
                for (int kk = 0; kk < 8; kk++) {
                    float4 e = ev[kk];
                    s += w[kk].x * e.x + w[kk].y * e.y
                       + w[kk].z * e.z + w[kk].w * e.w;
                }
                acc[rr] += s;
            }
        }
#pragma unroll
        for (int rr = 0; rr < 16; rr++)
            sE1[(rq * 16 + rr) * 132 + h] = acc[rr];
    }

    // ---- ef[p] = enc row p . fcW (y_tilde-without-ctx trick) ----
    {
        int c8 = lane & 7, pr = lane >> 3;
        int p  = (warp << 2) | pr;   // p = g*32 + t
        const float4* er = reinterpret_cast<const float4*>(sEnc + p * 132);
        const float4* fr = reinterpret_cast<const float4*>(sfc);
        float s = 0.f;
#pragma unroll
        for (int c = 0; c < 4; c++) {
            int idx = c * 8 + c8;
            float4 e = er[idx], f = fr[idx];
            s += e.x * f.x + e.y * f.y + e.z * f.z + e.w * f.w;
        }
        s += __shfl_xor_sync(0xffffffffu, s, 1);
        s += __shfl_xor_sync(0xffffffffu, s, 2);
        s += __shfl_xor_sync(0xffffffffu, s, 4);
        if (c8 == 0) sEf[p] = s;
    }

    // ---- A-MMA persistent W1_hc fragments in registers ----
    // warp w: m-tile mt = w&7 (rows j0..j0+15), k-half khA = w>>3 (8 k-tiles)
    const int mt  = warp & 7;
    const int khA = warp >> 3;
    const int j0  = mt << 4;
    unsigned aw0[8], aw1[8], aw2[8], aw3[8];
    {
        const float* r0p = W1 + (j0 + g8) * 384 + (khA << 7) + tg * 2;
        const float* r1p = r0p + 8 * 384;
#pragma unroll
        for (int kt = 0; kt < 8; kt++) {
            int k = kt * 16;
            aw0[kt] = packh2(r0p[k],     r0p[k + 1]);
            aw1[kt] = packh2(r1p[k],     r1p[k + 1]);
            aw2[kt] = packh2(r0p[k + 8], r0p[k + 9]);
            aw3[kt] = packh2(r1p[k + 8], r1p[k + 9]);
        }
    }
    // paired B-operand base: quad tg reads uint2 at +kt*16 halves
    const __half* bbRow = sHch + ((g8 < 2) ? g8 : 2) * HCS + tg * 4;

    // ---- F ldmatrix bases (Whh rows 32w..32w+31) ----
    const unsigned whBase = (unsigned)__cvta_generic_to_shared(sWh);
    const unsigned sA0 = whBase +
        (((warp << 5) | (lane & 15)) * 136 + ((lane >> 4) << 3)) * 2;
    const unsigned sA1 = sA0 + 16 * 136 * 2;
    __syncthreads();

    // per-thread constants for G' (valid for tid < 256)
    const float ef_reg = sEf[((tid >> 7) << 5) | lane];
    const float yco = sfc[128], ycb = sfc[129];
    // G' persistent indices + fp32 cell state in register
    const int jG = tid & 127, gG = tid >> 7;
    const int pA = ((jG >> 4) << 4) | pslot(jG & 15);   // paired addr of k=jG
    float c_reg = 0.f;

    for (int step = 0; step < TT; step++) {
        // ---- A: u[j,g] = W1_hc @ hc on tensor cores (A-frags in regs)
        {
            const __half* bA = bbRow + (khA << 7);
            float d0 = 0.f, d1 = 0.f, d2 = 0.f, d3 = 0.f;
            float f0 = 0.f, f1 = 0.f, f2 = 0.f, f3 = 0.f;
#pragma unroll
            for (int kt = 0; kt < 8; kt += 2) {
                uint2 bv = *reinterpret_cast<const uint2*>(bA + kt * 16);
                MMA16816(d0, d1, d2, d3,
                         aw0[kt], aw1[kt], aw2[kt], aw3[kt], bv.x, bv.y);
                uint2 cv = *reinterpret_cast<const uint2*>(bA + kt * 16 + 16);
                MMA16816(f0, f1, f2, f3,
                         aw0[kt + 1], aw1[kt + 1], aw2[kt + 1], aw3[kt + 1],
                         cv.x, cv.y);
            }
            if (tg == 0) {
                float* P = sup + (khA << 1) * 132;   // [khA][g][132]
                P[j0 + g8]             = d0 + f0;    // g0
                P[132 + j0 + g8]       = d1 + f1;    // g1
                P[j0 + g8 + 8]         = d2 + f2;
                P[132 + j0 + g8 + 8]   = d3 + f3;
            }
        }
        __syncthreads();

        // ---- B: 64 logits; warp covers 4 rows via 8-lane groups
        {
            int c8 = lane & 7, pr = lane >> 3;
            int p  = (warp << 2) | pr;
            int pg = p >> 5, pt = p & 31;
            const float4* e1r = reinterpret_cast<const float4*>(
                sE1 + (pg * 32 + pt) * 132);
            const float4* u0r = reinterpret_cast<const float4*>(sup + pg * 132);
            const float4* u1r = reinterpret_cast<const float4*>(sup + 264 + pg * 132);
            const float4* wr  = reinterpret_cast<const float4*>(sW2);
            float s = 0.f;
#pragma unroll
            for (int c = 0; c < 4; c++) {
                int idx = c * 8 + c8;
                float4 e = e1r[idx], ua = u0r[idx], ub = u1r[idx], w = wr[idx];
                s += fast_tanh(e.x + ua.x + ub.x) * w.x
                   + fast_tanh(e.y + ua.y + ub.y) * w.y
                   + fast_tanh(e.z + ua.z + ub.z) * w.z
                   + fast_tanh(e.w + ua.w + ub.w) * w.w;
            }
            s += __shfl_xor_sync(0xffffffffu, s, 1);
            s += __shfl_xor_sync(0xffffffffu, s, 2);
            s += __shfl_xor_sync(0xffffffffu, s, 4);
            if (c8 == 0) slogS[p] = s;
        }
        // ---- F: gates = Whh @ h on tensor cores (overlaps B, no barrier)
        {
            float d00 = 0.f, d01 = 0.f, d02 = 0.f, d03 = 0.f;
            float d10 = 0.f, d11 = 0.f, d12 = 0.f, d13 = 0.f;
#pragma unroll
            for (int kt = 0; kt < 8; kt++) {
                unsigned a0, a1, a2, a3, e0, e1, e2, e3;
                asm volatile(
                    "ldmatrix.sync.aligned.m8n8.x4.shared.b16 {%0,%1,%2,%3}, [%4];"
                    : "=r"(a0), "=r"(a1), "=r"(a2), "=r"(a3)
                    : "r"(sA0 + kt * 32));
                asm volatile(
                    "ldmatrix.sync.aligned.m8n8.x4.shared.b16 {%0,%1,%2,%3}, [%4];"
                    : "=r"(e0), "=r"(e1), "=r"(e2), "=r"(e3)
                    : "r"(sA1 + kt * 32));
                uint2 bv = *reinterpret_cast<const uint2*>(bbRow + kt * 16);
                MMA16816(d00, d01, d02, d03, a0, a1, a2, a3, bv.x, bv.y);
                MMA16816(d10, d11, d12, d13, e0, e1, e2, e3, bv.x, bv.y);
            }
            if (tg == 0) {   // cols 0,1 = batches 0,1
                int r0 = (warp << 5) | g8;
                sgates[r0]            = d00;  sgates[512 + r0]      = d01;
                sgates[r0 + 8]        = d02;  sgates[512 + r0 + 8]  = d03;
                sgates[r0 + 16]       = d10;  sgates[512 + r0 + 16] = d11;
                sgates[r0 + 24]       = d12;  sgates[512 + r0 + 24] = d13;
            }
        }
        __syncthreads();

        // ---- G': in-warp softmax + y_tilde + LSTM cell (8 warps)
        if (tid < 256) {
            // softmax over t = lane (logits bounded: no max pass needed)
            float l = slogS[(gG << 5) | lane];
            float e = __expf(l);
            float sum = e, wy = e * ef_reg;
#pragma unroll
            for (int o = 16; o > 0; o >>= 1) {
                sum += __shfl_xor_sync(0xffffffffu, sum, o);
                wy  += __shfl_xor_sync(0xffffffffu, wy, o);
            }
            float y = __fdividef(wy, sum) + sy[(gG << 5) | step] * yco + ycb;
            float gv[4];
#pragma unroll
            for (int q = 0; q < 4; q++) {
                int r = q * 128 + jG;
                gv[q] = sgates[gG * 512 + r] + sbias[r] + y * sWih[r];
            }
            float si = fast_sig(gv[0]);
            float sf = fast_sig(gv[1]);
            float so = fast_sig(gv[3]);
            float cn = sf * c_reg + si * fast_tanh(gv[2]);
            float hn = so * fast_tanh(cn);
            c_reg = cn;
            __half* hr = sHch + gG * HCS;
            hr[pA]       = __float2half(hn);
            hr[128 + pA] = __float2half(cn);
            if (step == TT - 1) {
                // fp32 h master only needed for the output dot
                int hq = jG >> 6, ho = jG & 63;
                sHp[gG * HB + hq * HQ + ho] = hn;
                if (((tid >> 5) & 3) == 0)
                    sAtt[(gG << 5) | lane] = __fdividef(e, sum);
            }
        }
        __syncthreads();
    }

    // ---- final ctx[g][j] = sum_t attn_t * enc[t][j]  (8 warps, once)
    if (warp < 8) {
        int g = warp >> 2;
        int j = ((warp & 3) << 5) | lane;
        const float* eb = sEnc + g * 32 * 132 + j;
        const float* ab = sAtt + g * 32;
        float acc = 0.f;
#pragma unroll
        for (int t = 0; t < 32; t++)
            acc = fmaf(ab[t], eb[t * 132], acc);
        sctxC[g * 128 + j] = acc;
    }
    __syncthreads();

    // ---- final: out[b] = [h, ctx] . fcfW + fcfb + y_history[b, 31]
    if (warp < 2) {
        int g = warp;
        float4 hv = reinterpret_cast<const float4*>(sHp + g * HB)
                        [(lane >> 4) * 17 + (lane & 15)];
        float4 f1 = reinterpret_cast<const float4*>(sfcf)[lane];
        float4 cv = reinterpret_cast<const float4*>(sctxC + g * 128)[lane];
        float4 f2 = reinterpret_cast<const float4*>(sfcf + 128)[lane];
        float s = hv.x * f1.x + hv.y * f1.y + hv.z * f1.z + hv.w * f1.w
                + cv.x * f2.x + cv.y * f2.y + cv.z * f2.z + cv.w * f2.w;
#pragma unroll
        for (int o = 16; o > 0; o >>= 1)
            s += __shfl_xor_sync(0xffffffffu, s, o);
        if (lane == 0)
            out[bp + g] = s + sfc[130] + sy[(g << 5) | 31];
    }
}

// ---------------------------------------------------------------------------
extern "C" void kernel_launch(void* const* d_in, const int* in_sizes, int n_in,
                              void* d_out, int out_size)
{
    const float* enc  = (const float*)d_in[0];
    const float* yh   = (const float*)d_in[1];
    const float* W1   = (const float*)d_in[2];
    const float* b1   = (const float*)d_in[3];
    const float* W2   = (const float*)d_in[4];
    // d_in[5] = attn_b2 : constant shift, cancels in softmax
    const float* Wih  = (const float*)d_in[6];
    const float* Whh  = (const float*)d_in[7];
    const float* bih  = (const float*)d_in[8];
    const float* bhh  = (const float*)d_in[9];
    const float* fcW  = (const float*)d_in[10];
    const float* fcb  = (const float*)d_in[11];
    const float* fcfW = (const float*)d_in[12];
    const float* fcfb = (const float*)d_in[13];
    float* out = (float*)d_out;

    const size_t smem_floats = 34816 + 8448 + 8448 + 552 + 1056 + 1024
                             + 528 + 256 + 512 + 512 + 128 + 256 + 132
                             + 64 + 64 + 64 + 64;
    const size_t smem = smem_floats * sizeof(float);   // 227,696 B

    cudaFuncSetAttribute(decoder_kernel,
                         cudaFuncAttributeMaxDynamicSharedMemorySize, (int)smem);
    cudaFuncSetAttribute(decoder_kernel,
                         cudaFuncAttributePreferredSharedMemoryCarveout, 100);

    whh_prep<<<8, 128>>>(Whh);
    decoder_kernel<<<128, 512, smem>>>(enc, yh, W1, b1, W2, Wih, bih, bhh,
                                       fcW, fcb, fcfW, fcfb, out);
}

// round 15
// speedup vs baseline: 1.1858x; 1.0433x over previous
#include <cuda_runtime.h>
#include <cuda_fp16.h>

#define BB 256
#define TT 32

// Device-global scratch: Whh fp16 row-major padded [512][136] (272B rows)
__device__ __half g_WhhH[512 * 136];

__device__ __forceinline__ float fast_tanh(float x) {
    float y;
    asm("tanh.approx.f32 %0, %1;" : "=f"(y) : "f"(x));
    return y;
}
__device__ __forceinline__ float fast_sig(float x) {
    return 0.5f + 0.5f * fast_tanh(0.5f * x);
}
__device__ __forceinline__ unsigned packh2(float x, float y) {
    __half2 h = __floats2half2_rn(x, y);
    return *reinterpret_cast<unsigned*>(&h);
}

#define MMA16816(d0,d1,d2,d3,a0,a1,a2,a3,b0,b1)                              \
    asm volatile(                                                            \
        "mma.sync.aligned.m16n8k16.row.col.f32.f16.f16.f32 "                 \
        "{%0,%1,%2,%3}, {%4,%5,%6,%7}, {%8,%9}, {%0,%1,%2,%3};"              \
        : "+f"(d0), "+f"(d1), "+f"(d2), "+f"(d3)                             \
        : "r"(a0), "r"(a1), "r"(a2), "r"(a3), "r"(b0), "r"(b1))

// fp32 h master: quarters of 64 floats at stride 68; batch stride 272.
#define HQ 68
#define HB 272
// fp16 hc shadow: rows = batch (8 rows, 2 real), 264 halves per row.
#define HCS 264

// ---------------------------------------------------------------------------
// Prep: Whh fp32 -> fp16 row-major padded [512][136]
// ---------------------------------------------------------------------------
__global__ void __launch_bounds__(128)
whh_prep(const float* __restrict__ Whh)   // [512,128]
{
    int base = blockIdx.x * 8704;
    for (int i = base + threadIdx.x; i < base + 8704; i += 128) {
        int r = i / 136, k = i % 136;
        g_WhhH[i] = __float2half((k < 128) ? Whh[r * 128 + k] : 0.f);
    }
}

// ---------------------------------------------------------------------------
// Main: 128 blocks x 512 threads, 2 batches/block. 3 barriers per step.
// A and F on tensor cores; ctx eliminated from loop; gates in [j][4q] layout.
// ---------------------------------------------------------------------------
__global__ void __launch_bounds__(512, 1)
decoder_kernel(const float* __restrict__ enc,     // [B,32,128]
               const float* __restrict__ yhist,   // [B,32]
               const float* __restrict__ W1,      // [128,384] cols [h|c|enc]
               const float* __restrict__ b1,      // [128]
               const float* __restrict__ W2,      // [128]
               const float* __restrict__ Wih,     // [512]
               const float* __restrict__ bih,     // [512]
               const float* __restrict__ bhh,     // [512]
               const float* __restrict__ fcW,     // [129]
               const float* __restrict__ fcb,     // [1]
               const float* __restrict__ fcfW,    // [256]
               const float* __restrict__ fcfb,    // [1]
               float* __restrict__ out)           // [256]
{
    extern __shared__ float sm[];
    __half* sWh   = (__half*)sm;          // [512][136] fp16 = 34816 fl
    float*  sEnc  = sm + 34816;           // 8448 [64 rows][132]
    float*  sE1   = sEnc + 8448;          // 8448 [64 rows][132]
    float*  sHp   = sE1 + 8448;           // 552  fp32 h master [g][q][68]
    __half* sHch  = (__half*)(sHp + 552); // [8][264] fp16 hc shadow = 1056 fl
    float*  sgates= sHp + 552 + 1056;     // 1024 [g][j][4q]
    float*  sup   = sgates + 1024;        // 528  [kh][g][132] u partials
    float*  sctxC = sup + 528;            // 256  [g][128] final ctx only
    float*  sWih  = sctxC + 256;          // 512  [j][4q]
    float*  sbias = sWih + 512;           // 512  [j][4q]
    float*  sW2   = sbias + 512;          // 128
    float*  sfcf  = sW2 + 128;            // 256
    float*  sfc   = sfcf + 256;           // 132: fcW[0..129), [129]=fcb, [130]=fcfb
    float*  sy    = sfc + 132;            // 64  [g][32]
    float*  slogS = sy + 64;              // 64
    float*  sEf   = slogS + 64;           // 64  [g][32] enc_t . fcW
    float*  sAtt  = sEf + 64;             // 64  [g][32] last-step attn

    const int tid  = threadIdx.x;
    const int lane = tid & 31;
    const int warp = tid >> 5;
    const int bp   = blockIdx.x * 2;

    // MMA lane coordinates
    const int tg = lane & 3;     // quad id (k selector)
    const int g8 = lane >> 2;    // group id (row / col-n selector)

    // ---- load phase ----
    for (int i = tid; i < 8704; i += 512)
        reinterpret_cast<uint4*>(sWh)[i] =
            reinterpret_cast<const uint4*>(g_WhhH)[i];
    for (int i4 = tid; i4 < 2048; i4 += 512) {
        int r = i4 >> 5, c = i4 & 31;
        reinterpret_cast<float4*>(sEnc)[r * 33 + c] =
            reinterpret_cast<const float4*>(enc + (size_t)bp * 4096)[i4];
    }
    {   // [j][4q] interleave: slot tid -> j = tid>>2, q = tid&3 -> row q*128+j
        int rI = ((tid & 3) << 7) | (tid >> 2);
        sWih[tid]  = Wih[rI];
        sbias[tid] = bih[rI] + bhh[rI];
    }
    if (tid < 552) sHp[tid] = 0.f;
    for (int i = tid; i < 1056; i += 512)
        reinterpret_cast<float*>(sHch)[i] = 0.f;
    if (tid < 128) sW2[tid]  = W2[tid];
    if (tid < 256) sfcf[tid] = fcfW[tid];
    if (tid < 131)
        sfc[tid] = (tid < 129) ? fcW[tid] : (tid == 129) ? fcb[0] : fcfb[0];
    if (tid < 64) sy[tid] = yhist[(bp + (tid >> 5)) * 32 + (tid & 31)];
    __syncthreads();

    // ---- E1 = enc @ W1e^T + b1, in-CTA once ----
    {
        int h = tid & 127, rq = tid >> 7;
        float acc[16];
        float bb = b1[h];
#pragma unroll
        for (int rr = 0; rr < 16; rr++) acc[rr] = bb;
        const float4* wsrc = reinterpret_cast<const float4*>(W1 + h * 384 + 256);
#pragma unroll
        for (int ch = 0; ch < 4; ch++) {
            float4 w[8];
#pragma unroll
            for (int kk = 0; kk < 8; kk++) w[kk] = wsrc[ch * 8 + kk];
#pragma unroll
            for (int rr = 0; rr < 16; rr++) {
                const float4* ev = reinterpret_cast<const float4*>(
                    sEnc + (rq * 16 + rr) * 132) + ch * 8;
                float s = 0.f;
#pragma unroll
                for (int kk = 0; kk < 8; kk++) {
                    float4 e = ev[kk];
                    s += w[kk].x * e.x + w[kk].y * e.y
                       + w[kk].z * e.z + w[kk].w * e.w;
                }
                acc[rr] += s;
            }
        }
#pragma unroll
        for (int rr = 0; rr < 16; rr++)
            sE1[(rq * 16 + rr) * 132 + h] = acc[rr];
    }

    // ---- ef[p] = enc row p . fcW (y_tilde-without-ctx trick) ----
    {
        int c8 = lane & 7, pr = lane >> 3;
        int p  = (warp << 2) | pr;   // p = g*32 + t
        const float4* er = reinterpret_cast<const float4*>(sEnc + p * 132);
        const float4* fr = reinterpret_cast<const float4*>(sfc);
        float s = 0.f;
#pragma unroll
        for (int c = 0; c < 4; c++) {
            int idx = c * 8 + c8;
            float4 e = er[idx], f = fr[idx];
            s += e.x * f.x + e.y * f.y + e.z * f.z + e.w * f.w;
        }
        s += __shfl_xor_sync(0xffffffffu, s, 1);
        s += __shfl_xor_sync(0xffffffffu, s, 2);
        s += __shfl_xor_sync(0xffffffffu, s, 4);
        if (c8 == 0) sEf[p] = s;
    }

    // ---- A-MMA persistent W1_hc fragments in registers ----
    // warp w: m-tile mt = w&7 (rows j0..j0+15), k-half khA = w>>3 (8 k-tiles)
    const int mt  = warp & 7;
    const int khA = warp >> 3;
    const int j0  = mt << 4;
    unsigned aw0[8], aw1[8], aw2[8], aw3[8];
    {
        const float* r0p = W1 + (j0 + g8) * 384 + (khA << 7) + tg * 2;
        const float* r1p = r0p + 8 * 384;
#pragma unroll
        for (int kt = 0; kt < 8; kt++) {
            int k = kt * 16;
            aw0[kt] = packh2(r0p[k],     r0p[k + 1]);
            aw1[kt] = packh2(r1p[k],     r1p[k + 1]);
            aw2[kt] = packh2(r0p[k + 8], r0p[k + 9]);
            aw3[kt] = packh2(r1p[k + 8], r1p[k + 9]);
        }
    }
    // shared B-operand row pointer (batch = g8; rows >=2 are zero)
    const __half* bbRow = sHch + ((g8 < 2) ? g8 : 2) * HCS + tg * 2;

    // ---- F ldmatrix bases (Whh rows 32w..32w+31) ----
    const unsigned whBase = (unsigned)__cvta_generic_to_shared(sWh);
    const unsigned sA0 = whBase +
        (((warp << 5) | (lane & 15)) * 136 + ((lane >> 4) << 3)) * 2;
    const unsigned sA1 = sA0 + 16 * 136 * 2;
    __syncthreads();

    // per-thread constants for G' (valid for tid < 256)
    const float ef_reg = sEf[((tid >> 7) << 5) | lane];
    const float yco = sfc[128], ycb = sfc[129];
    const int jG = tid & 127, gG = tid >> 7;
    float c_reg = 0.f;   // fp32 cell state lives in register

    for (int step = 0; step < TT; step++) {
        // ---- A: u[j,g] = W1_hc @ hc on tensor cores (A-frags in regs)
        {
            const __half* bA = bbRow + (khA << 7);
            float d0 = 0.f, d1 = 0.f, d2 = 0.f, d3 = 0.f;
            float f0 = 0.f, f1 = 0.f, f2 = 0.f, f3 = 0.f;
#pragma unroll
            for (int kt = 0; kt < 8; kt += 2) {
                unsigned b0 = *reinterpret_cast<const unsigned*>(bA + kt * 16);
                unsigned b1 = *reinterpret_cast<const unsigned*>(bA + kt * 16 + 8);
                MMA16816(d0, d1, d2, d3,
                         aw0[kt], aw1[kt], aw2[kt], aw3[kt], b0, b1);
                unsigned c0 = *reinterpret_cast<const unsigned*>(bA + kt * 16 + 16);
                unsigned c1 = *reinterpret_cast<const unsigned*>(bA + kt * 16 + 24);
                MMA16816(f0, f1, f2, f3,
                         aw0[kt + 1], aw1[kt + 1], aw2[kt + 1], aw3[kt + 1],
                         c0, c1);
            }
            if (tg == 0) {
                float* P = sup + (khA << 1) * 132;   // [khA][g][132]
                P[j0 + g8]             = d0 + f0;    // g0
                P[132 + j0 + g8]       = d1 + f1;    // g1
                P[j0 + g8 + 8]         = d2 + f2;
                P[132 + j0 + g8 + 8]   = d3 + f3;
            }
        }
        __syncthreads();

        // ---- F (loads + MMAs): gates = Whh @ h; stores deferred past B
        float d00 = 0.f, d01 = 0.f, d02 = 0.f, d03 = 0.f;
        float d10 = 0.f, d11 = 0.f, d12 = 0.f, d13 = 0.f;
        {
#pragma unroll
            for (int kt = 0; kt < 8; kt++) {
                unsigned a0, a1, a2, a3, e0, e1, e2, e3;
                asm volatile(
                    "ldmatrix.sync.aligned.m8n8.x4.shared.b16 {%0,%1,%2,%3}, [%4];"
                    : "=r"(a0), "=r"(a1), "=r"(a2), "=r"(a3)
                    : "r"(sA0 + kt * 32));
                asm volatile(
                    "ldmatrix.sync.aligned.m8n8.x4.shared.b16 {%0,%1,%2,%3}, [%4];"
                    : "=r"(e0), "=r"(e1), "=r"(e2), "=r"(e3)
                    : "r"(sA1 + kt * 32));
                unsigned b0 = *reinterpret_cast<const unsigned*>(bbRow + kt * 16);
                unsigned b1 = *reinterpret_cast<const unsigned*>(bbRow + kt * 16 + 8);
                MMA16816(d00, d01, d02, d03, a0, a1, a2, a3, b0, b1);
                MMA16816(d10, d11, d12, d13, e0, e1, e2, e3, b0, b1);
            }
        }

        // ---- B: 64 logits; warp covers 4 rows via 8-lane groups
        //      (HMMA latency of F drains underneath this MUFU block)
        {
            int c8 = lane & 7, pr = lane >> 3;
            int p  = (warp << 2) | pr;
            int pg = p >> 5, pt = p & 31;
            const float4* e1r = reinterpret_cast<const float4*>(
                sE1 + (pg * 32 + pt) * 132);
            const float4* u0r = reinterpret_cast<const float4*>(sup + pg * 132);
            const float4* u1r = reinterpret_cast<const float4*>(sup + 264 + pg * 132);
            const float4* wr  = reinterpret_cast<const float4*>(sW2);
            float s = 0.f;
#pragma unroll
            for (int c = 0; c < 4; c++) {
                int idx = c * 8 + c8;
                float4 e = e1r[idx], ua = u0r[idx], ub = u1r[idx], w = wr[idx];
                s += fast_tanh(e.x + ua.x + ub.x) * w.x
                   + fast_tanh(e.y + ua.y + ub.y) * w.y
                   + fast_tanh(e.z + ua.z + ub.z) * w.z
                   + fast_tanh(e.w + ua.w + ub.w) * w.w;
            }
            s += __shfl_xor_sync(0xffffffffu, s, 1);
            s += __shfl_xor_sync(0xffffffffu, s, 2);
            s += __shfl_xor_sync(0xffffffffu, s, 4);
            if (c8 == 0) slogS[p] = s;
        }

        // ---- F stores (interleaved [g][j][4q] layout)
        if (tg == 0) {
            int r0 = (warp << 5) | g8;
#pragma unroll
            for (int i = 0; i < 4; i++) {
                int r = r0 + (i << 3);
                int o = ((r & 127) << 2) | (r >> 7);
                float v0, v1;
                if (i == 0)      { v0 = d00; v1 = d01; }
                else if (i == 1) { v0 = d02; v1 = d03; }
                else if (i == 2) { v0 = d10; v1 = d11; }
                else             { v0 = d12; v1 = d13; }
                sgates[o]       = v0;   // batch 0
                sgates[512 + o] = v1;   // batch 1
            }
        }
        __syncthreads();

        // ---- G': in-warp softmax + y_tilde + LSTM cell (8 warps)
        if (tid < 256) {
            // softmax over t = lane (logits bounded: no max pass needed)
            float l = slogS[(gG << 5) | lane];
            float e = __expf(l);
            float sum = e, wy = e * ef_reg;
#pragma unroll
            for (int o = 16; o > 0; o >>= 1) {
                sum += __shfl_xor_sync(0xffffffffu, sum, o);
                wy  += __shfl_xor_sync(0xffffffffu, wy, o);
            }
            float y = __fdividef(wy, sum) + sy[(gG << 5) | step] * yco + ycb;
            float4 gg = reinterpret_cast<const float4*>(sgates + gG * 512)[jG];
            float4 bb = reinterpret_cast<const float4*>(sbias)[jG];
            float4 ww = reinterpret_cast<const float4*>(sWih)[jG];
            float gv0 = gg.x + bb.x + y * ww.x;
            float gv1 = gg.y + bb.y + y * ww.y;
            float gv2 = gg.z + bb.z + y * ww.z;
            float gv3 = gg.w + bb.w + y * ww.w;
            float si = fast_sig(gv0);
            float sf = fast_sig(gv1);
            float so = fast_sig(gv3);
            float cn = sf * c_reg + si * fast_tanh(gv2);
            float hn = so * fast_tanh(cn);
            c_reg = cn;
            __half* hr = sHch + gG * HCS;
            hr[jG]       = __float2half(hn);
            hr[128 + jG] = __float2half(cn);
            if (step == TT - 1) {
                int hq = jG >> 6, ho = jG & 63;
                sHp[gG * HB + hq * HQ + ho] = hn;
                if (((tid >> 5) & 3) == 0)
                    sAtt[(gG << 5) | lane] = __fdividef(e, sum);
            }
        }
        __syncthreads();
    }

    // ---- final ctx[g][j] = sum_t attn_t * enc[t][j]  (8 warps, once)
    if (warp < 8) {
        int g = warp >> 2;
        int j = ((warp & 3) << 5) | lane;
        const float* eb = sEnc + g * 32 * 132 + j;
        const float* ab = sAtt + g * 32;
        float acc = 0.f;
#pragma unroll
        for (int t = 0; t < 32; t++)
            acc = fmaf(ab[t], eb[t * 132], acc);
        sctxC[g * 128 + j] = acc;
    }
    __syncthreads();

    // ---- final: out[b] = [h, ctx] . fcfW + fcfb + y_history[b, 31]
    if (warp < 2) {
        int g = warp;
        float4 hv = reinterpret_cast<const float4*>(sHp + g * HB)
                        [(lane >> 4) * 17 + (lane & 15)];
        float4 f1 = reinterpret_cast<const float4*>(sfcf)[lane];
        float4 cv = reinterpret_cast<const float4*>(sctxC + g * 128)[lane];
        float4 f2 = reinterpret_cast<const float4*>(sfcf + 128)[lane];
        float s = hv.x * f1.x + hv.y * f1.y + hv.z * f1.z + hv.w * f1.w
                + cv.x * f2.x + cv.y * f2.y + cv.z * f2.z + cv.w * f2.w;
#pragma unroll
        for (int o = 16; o > 0; o >>= 1)
            s += __shfl_xor_sync(0xffffffffu, s, o);
        if (lane == 0)
            out[bp + g] = s + sfc[130] + sy[(g << 5) | 31];
    }
}

// ---------------------------------------------------------------------------
extern "C" void kernel_launch(void* const* d_in, const int* in_sizes, int n_in,
                              void* d_out, int out_size)
{
    const float* enc  = (const float*)d_in[0];
    const float* yh   = (const float*)d_in[1];
    const float* W1   = (const float*)d_in[2];
    const float* b1   = (const float*)d_in[3];
    const float* W2   = (const float*)d_in[4];
    // d_in[5] = attn_b2 : constant shift, cancels in softmax
    const float* Wih  = (const float*)d_in[6];
    const float* Whh  = (const float*)d_in[7];
    const float* bih  = (const float*)d_in[8];
    const float* bhh  = (const float*)d_in[9];
    const float* fcW  = (const float*)d_in[10];
    const float* fcb  = (const float*)d_in[11];
    const float* fcfW = (const float*)d_in[12];
    const float* fcfb = (const float*)d_in[13];
    float* out = (float*)d_out;

    const size_t smem_floats = 34816 + 8448 + 8448 + 552 + 1056 + 1024
                             + 528 + 256 + 512 + 512 + 128 + 256 + 132
                             + 64 + 64 + 64 + 64;
    const size_t smem = smem_floats * sizeof(float);   // 227,696 B

    cudaFuncSetAttribute(decoder_kernel,
                         cudaFuncAttributeMaxDynamicSharedMemorySize, (int)smem);
    cudaFuncSetAttribute(decoder_kernel,
                         cudaFuncAttributePreferredSharedMemoryCarveout, 100);

    whh_prep<<<8, 128>>>(Whh);
    decoder_kernel<<<128, 512, smem>>>(enc, yh, W1, b1, W2, Wih, bih, bhh,
                                       fcW, fcb, fcfW, fcfb, out);
}

// round 16
// speedup vs baseline: 1.2469x; 1.0516x over previous
#include <cuda_runtime.h>
#include <cuda_fp16.h>

#define BB 256
#define TT 32

__device__ __forceinline__ float fast_tanh(float x) {
    float y;
    asm("tanh.approx.f32 %0, %1;" : "=f"(y) : "f"(x));
    return y;
}
__device__ __forceinline__ float fast_sig(float x) {
    return 0.5f + 0.5f * fast_tanh(0.5f * x);
}
__device__ __forceinline__ unsigned packh2(float x, float y) {
    __half2 h = __floats2half2_rn(x, y);
    return *reinterpret_cast<unsigned*>(&h);
}

#define MMA16816(d0,d1,d2,d3,a0,a1,a2,a3,b0,b1)                              \
    asm volatile(                                                            \
        "mma.sync.aligned.m16n8k16.row.col.f32.f16.f16.f32 "                 \
        "{%0,%1,%2,%3}, {%4,%5,%6,%7}, {%8,%9}, {%0,%1,%2,%3};"              \
        : "+f"(d0), "+f"(d1), "+f"(d2), "+f"(d3)                             \
        : "r"(a0), "r"(a1), "r"(a2), "r"(a3), "r"(b0), "r"(b1))

// fp32 h master: quarters of 64 floats at stride 68; batch stride 272.
#define HQ 68
#define HB 272
// fp16 hc shadow: rows = batch (8 rows, 2 real), 264 halves per row.
#define HCS 264

// ---------------------------------------------------------------------------
// Main: 128 blocks x 512 threads, 2 batches/block. 3 barriers per step.
// A and F on tensor cores; softmax partials computed inside B.
// ---------------------------------------------------------------------------
__global__ void __launch_bounds__(512, 1)
decoder_kernel(const float* __restrict__ enc,     // [B,32,128]
               const float* __restrict__ yhist,   // [B,32]
               const float* __restrict__ W1,      // [128,384] cols [h|c|enc]
               const float* __restrict__ b1,      // [128]
               const float* __restrict__ W2,      // [128]
               const float* __restrict__ Wih,     // [512]
               const float* __restrict__ bih,     // [512]
               const float* __restrict__ bhh,     // [512]
               const float* __restrict__ Whh,     // [512,128]
               const float* __restrict__ fcW,     // [129]
               const float* __restrict__ fcb,     // [1]
               const float* __restrict__ fcfW,    // [256]
               const float* __restrict__ fcfb,    // [1]
               float* __restrict__ out)           // [256]
{
    extern __shared__ float sm[];
    __half* sWh   = (__half*)sm;          // [512][136] fp16 = 34816 fl
    float*  sEnc  = sm + 34816;           // 8448 [64 rows][132]
    float*  sE1   = sEnc + 8448;          // 8448 [64 rows][132]
    float*  sHp   = sE1 + 8448;           // 552  fp32 h master [g][q][68]
    __half* sHch  = (__half*)(sHp + 552); // [8][264] fp16 hc shadow = 1056 fl
    float*  sgates= sHp + 552 + 1056;     // 1024 [g][j][4q]
    float*  sup   = sgates + 1024;        // 528  [kh][g][132] u partials
    float*  sctxC = sup + 528;            // 256  [g][128] final ctx only
    float*  sWih  = sctxC + 256;          // 512  [j][4q]
    float*  sbias = sWih + 512;           // 512  [j][4q]
    float*  sW2   = sbias + 512;          // 128
    float*  sfcf  = sW2 + 128;            // 256
    float*  sfc   = sfcf + 256;           // 132: fcW[0..129), [129]=fcb, [130]=fcfb
    float*  sy    = sfc + 132;            // 64  [g][32]
    float*  slogS = sy + 64;              // 64  (last step only)
    float*  sEf   = slogS + 64;           // 64  [g][32] enc_t . fcW
    float*  sAtt  = sEf + 64;             // 64  [g][32] final attn
    float*  sPsum = sAtt + 64;            // 16  per-warp exp-sum partials
    float*  sPwy  = sPsum + 16;           // 16  per-warp exp*ef partials

    const int tid  = threadIdx.x;
    const int lane = tid & 31;
    const int warp = tid >> 5;
    const int bp   = blockIdx.x * 2;

    // MMA lane coordinates
    const int tg = lane & 3;     // quad id (k selector)
    const int g8 = lane >> 2;    // group id (row / col-n selector)

    // ---- load phase (Whh fp32 -> fp16 smem inline; no prep kernel) ----
    for (int i = tid; i < 512 * 32; i += 512) {
        int r = i >> 5, k4 = i & 31;
        float4 w = reinterpret_cast<const float4*>(Whh + r * 128)[k4];
        uint2 hv;
        hv.x = packh2(w.x, w.y);
        hv.y = packh2(w.z, w.w);
        *reinterpret_cast<uint2*>(sWh + r * 136 + k4 * 4) = hv;
    }
    {   // zero the 8-half padding of each Whh row
        int r = tid;   // 512 threads = 512 rows
        *reinterpret_cast<uint4*>(sWh + r * 136 + 128) = make_uint4(0, 0, 0, 0);
    }
    for (int i4 = tid; i4 < 2048; i4 += 512) {
        int r = i4 >> 5, c = i4 & 31;
        reinterpret_cast<float4*>(sEnc)[r * 33 + c] =
            reinterpret_cast<const float4*>(enc + (size_t)bp * 4096)[i4];
    }
    {   // [j][4q] interleave: slot tid -> j = tid>>2, q = tid&3 -> row q*128+j
        int rI = ((tid & 3) << 7) | (tid >> 2);
        sWih[tid]  = Wih[rI];
        sbias[tid] = bih[rI] + bhh[rI];
    }
    if (tid < 552) sHp[tid] = 0.f;
    for (int i = tid; i < 1056; i += 512)
        reinterpret_cast<float*>(sHch)[i] = 0.f;
    if (tid < 128) sW2[tid]  = W2[tid];
    if (tid < 256) sfcf[tid] = fcfW[tid];
    if (tid < 131)
        sfc[tid] = (tid < 129) ? fcW[tid] : (tid == 129) ? fcb[0] : fcfb[0];
    if (tid < 64) sy[tid] = yhist[(bp + (tid >> 5)) * 32 + (tid & 31)];
    __syncthreads();

    // ---- E1 = enc @ W1e^T + b1, in-CTA once ----
    {
        int h = tid & 127, rq = tid >> 7;
        float acc[16];
        float bb = b1[h];
#pragma unroll
        for (int rr = 0; rr < 16; rr++) acc[rr] = bb;
        const float4* wsrc = reinterpret_cast<const float4*>(W1 + h * 384 + 256);
#pragma unroll
        for (int ch = 0; ch < 4; ch++) {
            float4 w[8];
#pragma unroll
            for (int kk = 0; kk < 8; kk++) w[kk] = wsrc[ch * 8 + kk];
#pragma unroll
            for (int rr = 0; rr < 16; rr++) {
                const float4* ev = reinterpret_cast<const float4*>(
                    sEnc + (rq * 16 + rr) * 132) + ch * 8;
                float s = 0.f;
#pragma unroll
                for (int kk = 0; kk < 8; kk++) {
                    float4 e = ev[kk];
                    s += w[kk].x * e.x + w[kk].y * e.y
                       + w[kk].z * e.z + w[kk].w * e.w;
                }
                acc[rr] += s;
            }
        }
#pragma unroll
        for (int rr = 0; rr < 16; rr++)
            sE1[(rq * 16 + rr) * 132 + h] = acc[rr];
    }

    // ---- ef[p] = enc row p . fcW (y_tilde-without-ctx trick) ----
    {
        int c8 = lane & 7, pr = lane >> 3;
        int p  = (warp << 2) | pr;   // p = g*32 + t
        const float4* er = reinterpret_cast<const float4*>(sEnc + p * 132);
        const float4* fr = reinterpret_cast<const float4*>(sfc);
        float s = 0.f;
#pragma unroll
        for (int c = 0; c < 4; c++) {
            int idx = c * 8 + c8;
            float4 e = er[idx], f = fr[idx];
            s += e.x * f.x + e.y * f.y + e.z * f.z + e.w * f.w;
        }
        s += __shfl_xor_sync(0xffffffffu, s, 1);
        s += __shfl_xor_sync(0xffffffffu, s, 2);
        s += __shfl_xor_sync(0xffffffffu, s, 4);
        if (c8 == 0) sEf[p] = s;
    }

    // ---- A-MMA persistent W1_hc fragments in registers ----
    // warp w: m-tile mt = w&7 (rows j0..j0+15), k-half khA = w>>3 (8 k-tiles)
    const int mt  = warp & 7;
    const int khA = warp >> 3;
    const int j0  = mt << 4;
    unsigned aw0[8], aw1[8], aw2[8], aw3[8];
    {
        const float* r0p = W1 + (j0 + g8) * 384 + (khA << 7) + tg * 2;
        const float* r1p = r0p + 8 * 384;
#pragma unroll
        for (int kt = 0; kt < 8; kt++) {
            int k = kt * 16;
            aw0[kt] = packh2(r0p[k],     r0p[k + 1]);
            aw1[kt] = packh2(r1p[k],     r1p[k + 1]);
            aw2[kt] = packh2(r0p[k + 8], r0p[k + 9]);
            aw3[kt] = packh2(r1p[k + 8], r1p[k + 9]);
        }
    }
    // shared B-operand row pointer (batch = g8; rows >=2 are zero)
    const __half* bbRow = sHch + ((g8 < 2) ? g8 : 2) * HCS + tg * 2;

    // ---- F ldmatrix bases (Whh rows 32w..32w+31) ----
    const unsigned whBase = (unsigned)__cvta_generic_to_shared(sWh);
    const unsigned sA0 = whBase +
        (((warp << 5) | (lane & 15)) * 136 + ((lane >> 4) << 3)) * 2;
    const unsigned sA1 = sA0 + 16 * 136 * 2;
    __syncthreads();

    // per-thread constants for G' (valid for tid < 256)
    const float yco = sfc[128], ycb = sfc[129];
    const int jG = tid & 127, gG = tid >> 7;
    float c_reg = 0.f;   // fp32 cell state lives in register

    for (int step = 0; step < TT; step++) {
        // ---- A: u[j,g] = W1_hc @ hc on tensor cores (A-frags in regs)
        {
            const __half* bA = bbRow + (khA << 7);
            float d0 = 0.f, d1 = 0.f, d2 = 0.f, d3 = 0.f;
            float f0 = 0.f, f1 = 0.f, f2 = 0.f, f3 = 0.f;
#pragma unroll
            for (int kt = 0; kt < 8; kt += 2) {
                unsigned b0 = *reinterpret_cast<const unsigned*>(bA + kt * 16);
                unsigned b1 = *reinterpret_cast<const unsigned*>(bA + kt * 16 + 8);
                MMA16816(d0, d1, d2, d3,
                         aw0[kt], aw1[kt], aw2[kt], aw3[kt], b0, b1);
                unsigned c0 = *reinterpret_cast<const unsigned*>(bA + kt * 16 + 16);
                unsigned c1 = *reinterpret_cast<const unsigned*>(bA + kt * 16 + 24);
                MMA16816(f0, f1, f2, f3,
                         aw0[kt + 1], aw1[kt + 1], aw2[kt + 1], aw3[kt + 1],
                         c0, c1);
            }
            if (tg == 0) {
                float* P = sup + (khA << 1) * 132;   // [khA][g][132]
                P[j0 + g8]             = d0 + f0;    // g0
                P[132 + j0 + g8]       = d1 + f1;    // g1
                P[j0 + g8 + 8]         = d2 + f2;
                P[132 + j0 + g8 + 8]   = d3 + f3;
            }
        }
        __syncthreads();

        // ---- F (loads + MMAs): gates = Whh @ h; stores deferred past B
        float d00 = 0.f, d01 = 0.f, d02 = 0.f, d03 = 0.f;
        float d10 = 0.f, d11 = 0.f, d12 = 0.f, d13 = 0.f;
        {
#pragma unroll
            for (int kt = 0; kt < 8; kt++) {
                unsigned a0, a1, a2, a3, e0, e1, e2, e3;
                asm volatile(
                    "ldmatrix.sync.aligned.m8n8.x4.shared.b16 {%0,%1,%2,%3}, [%4];"
                    : "=r"(a0), "=r"(a1), "=r"(a2), "=r"(a3)
                    : "r"(sA0 + kt * 32));
                asm volatile(
                    "ldmatrix.sync.aligned.m8n8.x4.shared.b16 {%0,%1,%2,%3}, [%4];"
                    : "=r"(e0), "=r"(e1), "=r"(e2), "=r"(e3)
                    : "r"(sA1 + kt * 32));
                unsigned b0 = *reinterpret_cast<const unsigned*>(bbRow + kt * 16);
                unsigned b1 = *reinterpret_cast<const unsigned*>(bbRow + kt * 16 + 8);
                MMA16816(d00, d01, d02, d03, a0, a1, a2, a3, b0, b1);
                MMA16816(d10, d11, d12, d13, e0, e1, e2, e3, b0, b1);
            }
        }

        // ---- B: 64 logits + per-warp softmax partials
        {
            int c8 = lane & 7;
            int p  = (warp << 2) | (lane >> 3);
            int pg = p >> 5, pt = p & 31;
            const float4* e1r = reinterpret_cast<const float4*>(
                sE1 + (pg * 32 + pt) * 132);
            const float4* u0r = reinterpret_cast<const float4*>(sup + pg * 132);
            const float4* u1r = reinterpret_cast<const float4*>(sup + 264 + pg * 132);
            const float4* wr  = reinterpret_cast<const float4*>(sW2);
            float s = 0.f;
#pragma unroll
            for (int c = 0; c < 4; c++) {
                int idx = c * 8 + c8;
                float4 e = e1r[idx], ua = u0r[idx], ub = u1r[idx], w = wr[idx];
                s += fast_tanh(e.x + ua.x + ub.x) * w.x
                   + fast_tanh(e.y + ua.y + ub.y) * w.y
                   + fast_tanh(e.z + ua.z + ub.z) * w.z
                   + fast_tanh(e.w + ua.w + ub.w) * w.w;
            }
            s += __shfl_xor_sync(0xffffffffu, s, 1);
            s += __shfl_xor_sync(0xffffffffu, s, 2);
            s += __shfl_xor_sync(0xffffffffu, s, 4);
            // all lanes of 8-group now hold logit p; gather the warp's 4
            float l0 = __shfl_sync(0xffffffffu, s, 0);
            float l1 = __shfl_sync(0xffffffffu, s, 8);
            float l2 = __shfl_sync(0xffffffffu, s, 16);
            float l3 = __shfl_sync(0xffffffffu, s, 24);
            if (lane == 0) {
                float e0 = __expf(l0), e1 = __expf(l1);
                float e2 = __expf(l2), e3 = __expf(l3);
                const float* efp = sEf + (warp << 2);
                sPsum[warp] = (e0 + e1) + (e2 + e3);
                sPwy[warp]  = (e0 * efp[0] + e1 * efp[1])
                            + (e2 * efp[2] + e3 * efp[3]);
            }
            if (step == TT - 1 && c8 == 0) slogS[p] = s;
        }

        // ---- F stores (interleaved [g][j][4q] layout)
        if (tg == 0) {
            int r0 = (warp << 5) | g8;
#pragma unroll
            for (int i = 0; i < 4; i++) {
                int r = r0 + (i << 3);
                int o = ((r & 127) << 2) | (r >> 7);
                float v0, v1;
                if (i == 0)      { v0 = d00; v1 = d01; }
                else if (i == 1) { v0 = d02; v1 = d03; }
                else if (i == 2) { v0 = d10; v1 = d11; }
                else             { v0 = d12; v1 = d13; }
                sgates[o]       = v0;   // batch 0
                sgates[512 + o] = v1;   // batch 1
            }
        }
        __syncthreads();

        // ---- G': 3-shfl partial reduce + y_tilde + LSTM cell (8 warps)
        if (tid < 256) {
            float ps = sPsum[(gG << 3) | (lane & 7)];
            float pw = sPwy [(gG << 3) | (lane & 7)];
#pragma unroll
            for (int o = 1; o < 8; o <<= 1) {
                ps += __shfl_xor_sync(0xffffffffu, ps, o);
                pw += __shfl_xor_sync(0xffffffffu, pw, o);
            }
            float y = __fdividef(pw, ps) + sy[(gG << 5) | step] * yco + ycb;
            float4 gg = reinterpret_cast<const float4*>(sgates + gG * 512)[jG];
            float4 bb = reinterpret_cast<const float4*>(sbias)[jG];
            float4 ww = reinterpret_cast<const float4*>(sWih)[jG];
            float gv0 = gg.x + bb.x + y * ww.x;
            float gv1 = gg.y + bb.y + y * ww.y;
            float gv2 = gg.z + bb.z + y * ww.z;
            float gv3 = gg.w + bb.w + y * ww.w;
            float si = fast_sig(gv0);
            float sf = fast_sig(gv1);
            float so = fast_sig(gv3);
            float cn = sf * c_reg + si * fast_tanh(gv2);
            float hn = so * fast_tanh(cn);
            c_reg = cn;
            __half* hr = sHch + gG * HCS;
            hr[jG]       = __float2half(hn);
            hr[128 + jG] = __float2half(cn);
            if (step == TT - 1) {
                int hq = jG >> 6, ho = jG & 63;
                sHp[gG * HB + hq * HQ + ho] = hn;
            }
        }
        __syncthreads();
    }

    // ---- final attention from step-31 logits (warps 0,1), then ctx ----
    if (warp < 2) {
        float l = slogS[(warp << 5) | lane];
        float e = __expf(l);
        float sum = e;
#pragma unroll
        for (int o = 16; o > 0; o >>= 1)
            sum += __shfl_xor_sync(0xffffffffu, sum, o);
        sAtt[(warp << 5) | lane] = __fdividef(e, sum);
    }
    __syncthreads();

    // ---- final ctx[g][j] = sum_t attn_t * enc[t][j]  (8 warps, once)
    if (warp < 8) {
        int g = warp >> 2;
        int j = ((warp & 3) << 5) | lane;
        const float* eb = sEnc + g * 32 * 132 + j;
        const float* ab = sAtt + g * 32;
        float acc = 0.f;
#pragma unroll
        for (int t = 0; t < 32; t++)
            acc = fmaf(ab[t], eb[t * 132], acc);
        sctxC[g * 128 + j] = acc;
    }
    __syncthreads();

    // ---- final: out[b] = [h, ctx] . fcfW + fcfb + y_history[b, 31]
    if (warp < 2) {
        int g = warp;
        float4 hv = reinterpret_cast<const float4*>(sHp + g * HB)
                        [(lane >> 4) * 17 + (lane & 15)];
        float4 f1 = reinterpret_cast<const float4*>(sfcf)[lane];
        float4 cv = reinterpret_cast<const float4*>(sctxC + g * 128)[lane];
        float4 f2 = reinterpret_cast<const float4*>(sfcf + 128)[lane];
        float s = hv.x * f1.x + hv.y * f1.y + hv.z * f1.z + hv.w * f1.w
                + cv.x * f2.x + cv.y * f2.y + cv.z * f2.z + cv.w * f2.w;
#pragma unroll
        for (int o = 16; o > 0; o >>= 1)
            s += __shfl_xor_sync(0xffffffffu, s, o);
        if (lane == 0)
            out[bp + g] = s + sfc[130] + sy[(g << 5) | 31];
    }
}

// ---------------------------------------------------------------------------
extern "C" void kernel_launch(void* const* d_in, const int* in_sizes, int n_in,
                              void* d_out, int out_size)
{
    const float* enc  = (const float*)d_in[0];
    const float* yh   = (const float*)d_in[1];
    const float* W1   = (const float*)d_in[2];
    const float* b1   = (const float*)d_in[3];
    const float* W2   = (const float*)d_in[4];
    // d_in[5] = attn_b2 : constant shift, cancels in softmax
    const float* Wih  = (const float*)d_in[6];
    const float* Whh  = (const float*)d_in[7];
    const float* bih  = (const float*)d_in[8];
    const float* bhh  = (const float*)d_in[9];
    const float* fcW  = (const float*)d_in[10];
    const float* fcb  = (const float*)d_in[11];
    const float* fcfW = (const float*)d_in[12];
    const float* fcfb = (const float*)d_in[13];
    float* out = (float*)d_out;

    const size_t smem_floats = 34816 + 8448 + 8448 + 552 + 1056 + 1024
                             + 528 + 256 + 512 + 512 + 128 + 256 + 132
                             + 64 + 64 + 64 + 64 + 16 + 16;
    const size_t smem = smem_floats * sizeof(float);   // 227,824 B

    cudaFuncSetAttribute(decoder_kernel,
                         cudaFuncAttributeMaxDynamicSharedMemorySize, (int)smem);
    cudaFuncSetAttribute(decoder_kernel,
                         cudaFuncAttributePreferredSharedMemoryCarveout, 100);

    decoder_kernel<<<128, 512, smem>>>(enc, yh, W1, b1, W2, Wih, bih, bhh,
                                       Whh, fcW, fcb, fcfW, fcfb, out);
}